// round 3
// baseline (speedup 1.0000x reference)
#include <cuda_runtime.h>

// out[b,i,:] = c0[i]*H[b,base[i],:] + c1[i]*H[b,base[i]+1,:]
// coeff_kernel folds boundary extrapolation into (c0,c1,base) and packs the
// two bases of each output float4 (2 freqs) into one 32-bit word.
#define MAX_NFFT 8192
__device__ __align__(16) float2   g_coeff[MAX_NFFT];
__device__ __align__(16) unsigned g_bpack[MAX_NFFT / 2];

__global__ void coeff_kernel(const float* __restrict__ pilot_pos,
                             const float* __restrict__ decay_param,
                             int NP, int Nfft) {
    extern __shared__ float s_loc[];  // extended knots: [0, loc..., Nfft-1]
    const int tid = threadIdx.x;
    for (int k = tid; k < NP; k += blockDim.x)
        s_loc[k + 1] = pilot_pos[k] - 1.0f;
    if (tid == 0) {
        s_loc[0]      = 0.0f;
        s_loc[NP + 1] = (float)(Nfft - 1);
    }
    __syncthreads();

    float dp = decay_param[0];
    float decay = (dp > 20.0f) ? dp : log1pf(expf(dp));

    int i = blockIdx.x * blockDim.x + tid;
    if (i >= Nfft) return;
    float fi = (float)i;

    // searchsorted(loc_ext, i, side='right') - 1, clipped
    int lo = 0, hi = NP + 2;
    while (lo < hi) {
        int mid = (lo + hi) >> 1;
        if (s_loc[mid] <= fi) lo = mid + 1; else hi = mid;
    }
    int left = lo - 1;
    if (left < 0)  left = 0;
    if (left > NP) left = NP;

    float x0 = s_loc[left], x1 = s_loc[left + 1];
    float wl = expf(-decay * fabsf(fi - x0));
    float wr = expf(-decay * fabsf(x1 - fi));
    float w  = wl + wr + 1e-12f;
    float al = wl / w, ar = wr / w;

    float c0, c1;
    int base;
    if (left == 0) {
        // y0 = h0 = (1+t)*H[0] - t*H[1], t = loc0/(loc1-loc0); y1 = H[0]
        float l0 = s_loc[1], l1 = s_loc[2];
        float t = l0 / (l1 - l0);
        base = 0;
        c0 = al * (1.0f + t) + ar;
        c1 = -al * t;
    } else if (left == NP) {
        // y0 = H[NP-1]; y1 = hN = (1+u)*H[NP-1] - u*H[NP-2]
        float lN1 = s_loc[NP], lN2 = s_loc[NP - 1];
        float u = ((float)(Nfft - 1) - lN1) / (lN1 - lN2);
        base = NP - 2;
        c0 = -ar * u;
        c1 = al + ar * (1.0f + u);
    } else {
        base = left - 1;
        c0 = al;
        c1 = ar;
    }
    g_coeff[i] = make_float2(c0, c1);

    // Pack bases of freqs (2t, 2t+1) into one word. Pairs never straddle a
    // warp (warp covers 32 consecutive i), so shfl_down from lane i+1 works.
    unsigned b_me  = (unsigned)base;
    unsigned b_nxt = __shfl_down_sync(0xffffffffu, b_me, 1);
    if ((i & 1) == 0)
        g_bpack[i >> 1] = (b_me & 0xffffu) | (b_nxt << 16);
}

// One block per batch row b. sPair[k] = (H[k], H[k+1]) staged as aligned
// float4 so each output pair costs 2 broadcast LDS.128, then warp-contiguous
// float4 streaming stores.
__global__ void __launch_bounds__(256, 6)
interp_kernel(const float2* __restrict__ H,   // [B, NP]
              float* __restrict__ out,        // [B, Nfft, 2]
              int NP, int nf4) {               // nf4 = Nfft/2
    extern __shared__ float4 sPair[];          // NP-1 used entries
    const int tid = threadIdx.x;
    const int b   = blockIdx.x;

    const float2* Hrow = H + (size_t)b * NP;
    for (int k = tid; k < NP - 1; k += blockDim.x) {
        float2 a = __ldg(Hrow + k);
        float2 c = __ldg(Hrow + k + 1);
        sPair[k] = make_float4(a.x, a.y, c.x, c.y);
    }
    __syncthreads();

    const float4*   c4 = (const float4*)g_coeff;  // 2 coeff pairs / float4
    const unsigned* bp = g_bpack;
    float4* orow = (float4*)out + (size_t)b * nf4;

    #pragma unroll 4
    for (int f4 = tid; f4 < nf4; f4 += blockDim.x) {
        float4   c  = c4[f4];
        unsigned pk = bp[f4];
        float4 y0 = sPair[pk & 0xffffu];
        float4 y1 = sPair[pk >> 16];

        float4 r;
        r.x = c.x * y0.x + c.y * y0.z;
        r.y = c.x * y0.y + c.y * y0.w;
        r.z = c.z * y1.x + c.w * y1.z;
        r.w = c.z * y1.y + c.w * y1.w;

        __stcs(orow + f4, r);   // streaming store: output never re-read
    }
}

extern "C" void kernel_launch(void* const* d_in, const int* in_sizes, int n_in,
                              void* d_out, int out_size) {
    const float* LS_ri       = (const float*)d_in[0];  // [B, NP, 2]
    const float* pilot_pos   = (const float*)d_in[1];  // [NP]
    const float* decay_param = (const float*)d_in[2];  // [1]
    int NP   = in_sizes[1];
    int B    = in_sizes[0] / (NP * 2);
    int Nfft = out_size / (B * 2);

    // Kernel A: per-frequency coefficient + packed-base tables (tiny).
    {
        int threads = 256;
        int blocks  = (Nfft + threads - 1) / threads;
        size_t smem = (size_t)(NP + 2) * sizeof(float);
        coeff_kernel<<<blocks, threads, smem>>>(pilot_pos, decay_param, NP, Nfft);
    }

    // Kernel B: one block per batch row, paired taps in smem.
    {
        int nf4 = Nfft / 2;
        dim3 block(256);
        dim3 grid(B);
        size_t smem = (size_t)NP * sizeof(float4);
        interp_kernel<<<grid, block, smem>>>((const float2*)LS_ri, (float*)d_out,
                                             NP, nf4);
    }
}